// round 1
// baseline (speedup 1.0000x reference)
#include <cuda_runtime.h>

#define BB  32
#define SS  2048
#define DD  768
#define QDIM 256
#define ODIM 1024

// -------- scratch (allocation-free: __device__ globals) --------
__device__ float g_Q[(size_t)BB * SS * QDIM];      // Q, later reused as X (attn output)
__device__ float g_K[(size_t)BB * SS * QDIM];      // K
__device__ float g_SC[(size_t)BB * SS * SS];       // scores / attn (512 MB)
__device__ float g_PART[BB * 16 * QDIM];           // maxpool partials

// ============================================================================
// Generic 128x128x8 SGEMM, 256 threads, 8x8 microtile.
//   BT = true : C[m,n] = sum_k A[m,k] * B[n,k]   (B is [N,K] row-major, "NT")
//   BT = false: C[m,n] = sum_k A[m,k] * B[k,n]   (B is [K,N] row-major, "NN")
// C[m,n] = acc*scale + (bias ? bias[n] : 0).  lda=K, ldb=(BT?K:N), ldc=N.
// Requires M%128==0, N%128==0, K%8==0 (true for all uses here).
// ============================================================================
template <bool BT>
__global__ __launch_bounds__(256) void sgemm128(
    const float* __restrict__ A, const float* __restrict__ Bm,
    const float* __restrict__ bias, float* __restrict__ C,
    int M, int N, int K, float scale,
    size_t sA, size_t sB, size_t sC)
{
    __shared__ float As[8][132];   // pad to 132: conflict-free stores, 16B-aligned rows
    __shared__ float Bs[8][132];

    A  += (size_t)blockIdx.z * sA;
    Bm += (size_t)blockIdx.z * sB;
    C  += (size_t)blockIdx.z * sC;

    const int tid = threadIdx.x;
    const int bm  = blockIdx.y * 128;
    const int bn  = blockIdx.x * 128;
    const int tx  = tid & 15;
    const int ty  = tid >> 4;

    // A-tile (and NT B-tile) loader indices: 128 rows x 8 k, float4 along k
    const int lrow = tid >> 1;          // 0..127
    const int lk   = (tid & 1) * 4;     // 0 or 4
    // NN B-tile loader indices: 8 k-rows x 128 n, float4 along n
    const int nk   = tid >> 5;          // 0..7
    const int nn   = (tid & 31) * 4;    // 0..124

    float acc[8][8] = {{0.f}};

    for (int k0 = 0; k0 < K; k0 += 8) {
        float4 av = *(const float4*)(A + (size_t)(bm + lrow) * K + k0 + lk);
        As[lk + 0][lrow] = av.x;
        As[lk + 1][lrow] = av.y;
        As[lk + 2][lrow] = av.z;
        As[lk + 3][lrow] = av.w;

        if (BT) {
            float4 bv = *(const float4*)(Bm + (size_t)(bn + lrow) * K + k0 + lk);
            Bs[lk + 0][lrow] = bv.x;
            Bs[lk + 1][lrow] = bv.y;
            Bs[lk + 2][lrow] = bv.z;
            Bs[lk + 3][lrow] = bv.w;
        } else {
            float4 bv = *(const float4*)(Bm + (size_t)(k0 + nk) * N + bn + nn);
            Bs[nk][nn + 0] = bv.x;
            Bs[nk][nn + 1] = bv.y;
            Bs[nk][nn + 2] = bv.z;
            Bs[nk][nn + 3] = bv.w;
        }
        __syncthreads();

        #pragma unroll
        for (int k = 0; k < 8; k++) {
            float a[8], b[8];
            *(float4*)(a)     = *(const float4*)&As[k][ty * 4];
            *(float4*)(a + 4) = *(const float4*)&As[k][64 + ty * 4];
            *(float4*)(b)     = *(const float4*)&Bs[k][tx * 4];
            *(float4*)(b + 4) = *(const float4*)&Bs[k][64 + tx * 4];
            #pragma unroll
            for (int i = 0; i < 8; i++)
                #pragma unroll
                for (int j = 0; j < 8; j++)
                    acc[i][j] += a[i] * b[j];
        }
        __syncthreads();
    }

    // epilogue: scale + optional bias, float4 stores
    #pragma unroll
    for (int ih = 0; ih < 2; ih++) {
        #pragma unroll
        for (int i = 0; i < 4; i++) {
            const int row = bm + ih * 64 + ty * 4 + i;
            #pragma unroll
            for (int jh = 0; jh < 2; jh++) {
                const int col = bn + jh * 64 + tx * 4;
                float4 v;
                v.x = acc[ih * 4 + i][jh * 4 + 0] * scale;
                v.y = acc[ih * 4 + i][jh * 4 + 1] * scale;
                v.z = acc[ih * 4 + i][jh * 4 + 2] * scale;
                v.w = acc[ih * 4 + i][jh * 4 + 3] * scale;
                if (bias) {
                    v.x += bias[col + 0];
                    v.y += bias[col + 1];
                    v.z += bias[col + 2];
                    v.w += bias[col + 3];
                }
                *(float4*)(C + (size_t)row * N + col) = v;
            }
        }
    }
}

// ============================================================================
// Row softmax over S=2048, one CTA (128 threads) per row, row kept in regs.
// ============================================================================
__global__ __launch_bounds__(128) void softmax_rows(float* __restrict__ sc)
{
    float* p = sc + (size_t)blockIdx.x * SS;
    const int tid = threadIdx.x;

    float v[16];
    float m = -INFINITY;
    #pragma unroll
    for (int i = 0; i < 16; i++) { v[i] = p[tid + i * 128]; m = fmaxf(m, v[i]); }

    __shared__ float redm[4];
    #pragma unroll
    for (int o = 16; o > 0; o >>= 1) m = fmaxf(m, __shfl_xor_sync(0xffffffffu, m, o));
    if ((tid & 31) == 0) redm[tid >> 5] = m;
    __syncthreads();
    m = fmaxf(fmaxf(redm[0], redm[1]), fmaxf(redm[2], redm[3]));

    float s = 0.f;
    #pragma unroll
    for (int i = 0; i < 16; i++) { v[i] = __expf(v[i] - m); s += v[i]; }

    __shared__ float reds[4];
    #pragma unroll
    for (int o = 16; o > 0; o >>= 1) s += __shfl_xor_sync(0xffffffffu, s, o);
    if ((tid & 31) == 0) reds[tid >> 5] = s;
    __syncthreads();
    s = (reds[0] + reds[1]) + (reds[2] + reds[3]);

    const float inv = 1.f / s;
    #pragma unroll
    for (int i = 0; i < 16; i++) p[tid + i * 128] = v[i] * inv;
}

// ============================================================================
// Maxpool stage 1: per (b, chunk of 128 seq rows), max over rows -> g_PART
// ============================================================================
__global__ __launch_bounds__(256) void maxpool_partial(const float* __restrict__ X)
{
    const int b = blockIdx.x;
    const int c = blockIdx.y;
    const float* p = X + ((size_t)b * SS + (size_t)c * 128) * QDIM + threadIdx.x;
    float m = -INFINITY;
    #pragma unroll 8
    for (int s = 0; s < 128; s++) m = fmaxf(m, p[(size_t)s * QDIM]);
    g_PART[((size_t)b * 16 + c) * QDIM + threadIdx.x] = m;
}

// ============================================================================
// Final: reduce partial maxes -> x[b,:]; out[b,o] = relu(x . W3[o,:] + b3[o])
// ============================================================================
__global__ __launch_bounds__(256) void final_head(
    const float* __restrict__ W3, const float* __restrict__ b3,
    float* __restrict__ out)
{
    const int b = blockIdx.x;
    const int tid = threadIdx.x;
    __shared__ float xs[QDIM];

    float m = -INFINITY;
    #pragma unroll
    for (int c = 0; c < 16; c++)
        m = fmaxf(m, g_PART[((size_t)b * 16 + c) * QDIM + tid]);
    xs[tid] = m;
    __syncthreads();

    #pragma unroll
    for (int kk = 0; kk < 4; kk++) {
        const int o = tid + kk * 256;
        const float4* w = (const float4*)(W3 + (size_t)o * QDIM);
        float acc = 0.f;
        #pragma unroll
        for (int q = 0; q < QDIM / 4; q++) {
            float4 wv = w[q];
            acc += wv.x * xs[q * 4 + 0] + wv.y * xs[q * 4 + 1]
                 + wv.z * xs[q * 4 + 2] + wv.w * xs[q * 4 + 3];
        }
        out[(size_t)b * ODIM + o] = fmaxf(acc + b3[o], 0.f);
    }
}

// ============================================================================
extern "C" void kernel_launch(void* const* d_in, const int* in_sizes, int n_in,
                              void* d_out, int out_size)
{
    const float* data = (const float*)d_in[0];
    /* d_in[1] = seq_len: unused by the reference */
    const float* W1 = (const float*)d_in[2];
    const float* b1 = (const float*)d_in[3];
    const float* W2 = (const float*)d_in[4];
    const float* b2 = (const float*)d_in[5];
    const float* W3 = (const float*)d_in[6];
    const float* b3 = (const float*)d_in[7];
    float* out = (float*)d_out;

    float *Q, *K, *SC;
    cudaGetSymbolAddress((void**)&Q,  g_Q);
    cudaGetSymbolAddress((void**)&K,  g_K);
    cudaGetSymbolAddress((void**)&SC, g_SC);

    const size_t strQK = (size_t)SS * QDIM;
    const size_t strSC = (size_t)SS * SS;
    const float  inv_sqrt_qd = 1.0f / 16.0f;   // 1/sqrt(256)

    // 1) Q = data @ W1^T + b1   [65536 x 256], K likewise
    sgemm128<true><<<dim3(QDIM / 128, (BB * SS) / 128, 1), 256>>>(
        data, W1, b1, Q, BB * SS, QDIM, DD, 1.0f, 0, 0, 0);
    sgemm128<true><<<dim3(QDIM / 128, (BB * SS) / 128, 1), 256>>>(
        data, W2, b2, K, BB * SS, QDIM, DD, 1.0f, 0, 0, 0);

    // 2) scores[b] = (K[b] @ Q[b]^T) / sqrt(QD)   [2048 x 2048] per batch
    sgemm128<true><<<dim3(SS / 128, SS / 128, BB), 256>>>(
        K, Q, nullptr, SC, SS, SS, QDIM, inv_sqrt_qd, strQK, strQK, strSC);

    // 3) softmax over last dim, in place
    softmax_rows<<<BB * SS, 128>>>(SC);

    // 4) X[b] = attn[b] @ K[b]   [2048 x 256]; reuse Q buffer as X
    sgemm128<false><<<dim3(QDIM / 128, SS / 128, BB), 256>>>(
        SC, K, nullptr, Q, SS, QDIM, SS, 1.0f, strSC, strQK, strQK);

    // 5) maxpool over sequence (two-stage)
    maxpool_partial<<<dim3(BB, 16), 256>>>(Q);

    // 6) out = relu(xmax @ W3^T + b3)
    final_head<<<BB, 256>>>(W3, b3, out);
}

// round 3
// speedup vs baseline: 1.5342x; 1.5342x over previous
#include <cuda_runtime.h>
#include <cstdint>

#define BB  32
#define SS  2048
#define DD  768
#define QDIM 256
#define ODIM 1024

// -------- scratch (allocation-free: __device__ globals) --------
__device__ float g_Q[(size_t)BB * SS * QDIM];      // Q, later reused as X (attn output)
__device__ float g_K[(size_t)BB * SS * QDIM];      // K
__device__ float g_SC[(size_t)BB * SS * SS];       // scores / attn (512 MB)
__device__ float g_PART[BB * 16 * QDIM];           // maxpool partials

__device__ __forceinline__ uint32_t f2tf32(float x) {
    uint32_t u;
    asm("cvt.rna.tf32.f32 %0, %1;" : "=r"(u) : "f"(x));
    return u;
}

__device__ __forceinline__ void mma8(float* d, const uint32_t* a, const uint32_t* b) {
    asm volatile(
        "mma.sync.aligned.m16n8k8.row.col.f32.tf32.tf32.f32 "
        "{%0,%1,%2,%3}, {%4,%5,%6,%7}, {%8,%9}, {%0,%1,%2,%3};"
        : "+f"(d[0]), "+f"(d[1]), "+f"(d[2]), "+f"(d[3])
        : "r"(a[0]), "r"(a[1]), "r"(a[2]), "r"(a[3]), "r"(b[0]), "r"(b[1]));
}

// ============================================================================
// tf32 mma.sync GEMM, CTA tile 128x128, k-chunk 32, 256 threads (8 warps 2x4),
// warp tile 64x32 (4x m16 x 4x n8).
//   BT=true : C[m,n] = scale * sum_k A[m,k]*B[n,k] + bias[n]   (B row-major [N,K])
//   BT=false: C[m,n] = scale * sum_k A[m,k]*B[k,n] + bias[n]   (B row-major [K,N])
// Smem layout [k][136] (pad -> k-stride = 8 banks): conflict-free LDS + STS.
// Requires M%128==0, N%128==0, kdim%32==0.
// ============================================================================
template <bool BT>
__global__ __launch_bounds__(256) void mma_gemm(
    const float* __restrict__ A, const float* __restrict__ B,
    const float* __restrict__ bias, float* __restrict__ C,
    int lda, int ldb, int ldc, int kdim, float scale,
    size_t sA, size_t sB, size_t sC)
{
    __shared__ uint32_t As[32][136];
    __shared__ uint32_t Bs[32][136];

    A += (size_t)blockIdx.z * sA;
    B += (size_t)blockIdx.z * sB;
    C += (size_t)blockIdx.z * sC;
    const int bm = blockIdx.y * 128;
    const int bn = blockIdx.x * 128;

    const int tid  = threadIdx.x;
    const int lane = tid & 31;
    const int wid  = tid >> 5;
    const int wm   = wid & 1;          // 0..1  -> warp row (64 m each)
    const int wn   = wid >> 1;         // 0..3  -> warp col (32 n each)
    const int qd   = lane >> 2;        // 0..7
    const int cc   = lane & 3;         // 0..3

    // A loader (also B loader for NT): row = tid&127, k-half = (tid>>7)*16
    const int lrow = tid & 127;
    const int lkh  = (tid >> 7) * 16;
    const float* pa   = A + (size_t)(bm + lrow) * lda + lkh;
    const float* pbNT = B + (size_t)(bn + lrow) * ldb + lkh;
    // NN B loader: k0 = tid>>5 (+ i*8), n = (tid&31)*4
    const int bk0 = tid >> 5;
    const int bn4 = (lane) * 4;
    const float* pbNN = B + (size_t)bk0 * ldb + bn + bn4;

    float acc[4][4][4];
#pragma unroll
    for (int i = 0; i < 4; i++)
#pragma unroll
        for (int j = 0; j < 4; j++)
#pragma unroll
            for (int r = 0; r < 4; r++) acc[i][j][r] = 0.f;

    float4 ra[4], rb[4];
    // preload chunk 0
#pragma unroll
    for (int i = 0; i < 4; i++) ra[i] = *(const float4*)(pa + i * 4);
    if (BT) {
#pragma unroll
        for (int i = 0; i < 4; i++) rb[i] = *(const float4*)(pbNT + i * 4);
    } else {
#pragma unroll
        for (int i = 0; i < 4; i++) rb[i] = *(const float4*)(pbNN + (size_t)(i * 8) * ldb);
    }

    const int nc = kdim >> 5;
    for (int ch = 0; ch < nc; ch++) {
        if (ch) __syncthreads();   // previous compute done reading smem

        // store chunk (with tf32 conversion)
#pragma unroll
        for (int i = 0; i < 4; i++) {
            As[lkh + i * 4 + 0][lrow] = f2tf32(ra[i].x);
            As[lkh + i * 4 + 1][lrow] = f2tf32(ra[i].y);
            As[lkh + i * 4 + 2][lrow] = f2tf32(ra[i].z);
            As[lkh + i * 4 + 3][lrow] = f2tf32(ra[i].w);
        }
        if (BT) {
#pragma unroll
            for (int i = 0; i < 4; i++) {
                Bs[lkh + i * 4 + 0][lrow] = f2tf32(rb[i].x);
                Bs[lkh + i * 4 + 1][lrow] = f2tf32(rb[i].y);
                Bs[lkh + i * 4 + 2][lrow] = f2tf32(rb[i].z);
                Bs[lkh + i * 4 + 3][lrow] = f2tf32(rb[i].w);
            }
        } else {
#pragma unroll
            for (int i = 0; i < 4; i++) {
                uint4 v;
                v.x = f2tf32(rb[i].x); v.y = f2tf32(rb[i].y);
                v.z = f2tf32(rb[i].z); v.w = f2tf32(rb[i].w);
                *(uint4*)&Bs[bk0 + i * 8][bn4] = v;   // STS.128, conflict-free
            }
        }
        __syncthreads();

        // prefetch next chunk into registers (hidden under compute)
        if (ch + 1 < nc) {
            const int k0 = (ch + 1) << 5;
#pragma unroll
            for (int i = 0; i < 4; i++) ra[i] = *(const float4*)(pa + k0 + i * 4);
            if (BT) {
#pragma unroll
                for (int i = 0; i < 4; i++) rb[i] = *(const float4*)(pbNT + k0 + i * 4);
            } else {
#pragma unroll
                for (int i = 0; i < 4; i++)
                    rb[i] = *(const float4*)(pbNN + (size_t)(k0 + i * 8) * ldb);
            }
        }

        // compute 4 k-slices of 8
#pragma unroll
        for (int ks = 0; ks < 4; ks++) {
            const int k0 = ks * 8 + cc;
            uint32_t af[4][4], bf[4][2];
#pragma unroll
            for (int mt = 0; mt < 4; mt++) {
                const int m = wm * 64 + mt * 16 + qd;
                af[mt][0] = As[k0][m];
                af[mt][1] = As[k0][m + 8];
                af[mt][2] = As[k0 + 4][m];
                af[mt][3] = As[k0 + 4][m + 8];
            }
#pragma unroll
            for (int nt = 0; nt < 4; nt++) {
                const int n = wn * 32 + nt * 8 + qd;
                bf[nt][0] = Bs[k0][n];
                bf[nt][1] = Bs[k0 + 4][n];
            }
#pragma unroll
            for (int mt = 0; mt < 4; mt++)
#pragma unroll
                for (int nt = 0; nt < 4; nt++)
                    mma8(acc[mt][nt], af[mt], bf[nt]);
        }
    }

    // epilogue: scale + optional bias, float2 stores
#pragma unroll
    for (int mt = 0; mt < 4; mt++) {
        const int m0 = bm + wm * 64 + mt * 16 + qd;
#pragma unroll
        for (int nt = 0; nt < 4; nt++) {
            const int n = bn + wn * 32 + nt * 8 + cc * 2;
            float bx = 0.f, by = 0.f;
            if (bias) { bx = bias[n]; by = bias[n + 1]; }
            float2 v0, v1;
            v0.x = acc[mt][nt][0] * scale + bx;
            v0.y = acc[mt][nt][1] * scale + by;
            v1.x = acc[mt][nt][2] * scale + bx;
            v1.y = acc[mt][nt][3] * scale + by;
            *(float2*)(C + (size_t)m0 * ldc + n)       = v0;
            *(float2*)(C + (size_t)(m0 + 8) * ldc + n) = v1;
        }
    }
}

// ============================================================================
// Row softmax over S=2048, one CTA (128 threads) per row, row kept in regs.
// ============================================================================
__global__ __launch_bounds__(128) void softmax_rows(float* __restrict__ sc)
{
    float* p = sc + (size_t)blockIdx.x * SS;
    const int tid = threadIdx.x;

    float v[16];
    float m = -INFINITY;
#pragma unroll
    for (int i = 0; i < 16; i++) { v[i] = p[tid + i * 128]; m = fmaxf(m, v[i]); }

    __shared__ float redm[4];
#pragma unroll
    for (int o = 16; o > 0; o >>= 1) m = fmaxf(m, __shfl_xor_sync(0xffffffffu, m, o));
    if ((tid & 31) == 0) redm[tid >> 5] = m;
    __syncthreads();
    m = fmaxf(fmaxf(redm[0], redm[1]), fmaxf(redm[2], redm[3]));

    float s = 0.f;
#pragma unroll
    for (int i = 0; i < 16; i++) { v[i] = __expf(v[i] - m); s += v[i]; }

    __shared__ float reds[4];
#pragma unroll
    for (int o = 16; o > 0; o >>= 1) s += __shfl_xor_sync(0xffffffffu, s, o);
    if ((tid & 31) == 0) reds[tid >> 5] = s;
    __syncthreads();
    s = (reds[0] + reds[1]) + (reds[2] + reds[3]);

    const float inv = 1.f / s;
#pragma unroll
    for (int i = 0; i < 16; i++) p[tid + i * 128] = v[i] * inv;
}

// ============================================================================
__global__ __launch_bounds__(256) void maxpool_partial(const float* __restrict__ X)
{
    const int b = blockIdx.x;
    const int c = blockIdx.y;
    const float* p = X + ((size_t)b * SS + (size_t)c * 128) * QDIM + threadIdx.x;
    float m = -INFINITY;
#pragma unroll 8
    for (int s = 0; s < 128; s++) m = fmaxf(m, p[(size_t)s * QDIM]);
    g_PART[((size_t)b * 16 + c) * QDIM + threadIdx.x] = m;
}

__global__ __launch_bounds__(256) void final_head(
    const float* __restrict__ W3, const float* __restrict__ b3,
    float* __restrict__ out)
{
    const int b = blockIdx.x;
    const int tid = threadIdx.x;
    __shared__ float xs[QDIM];

    float m = -INFINITY;
#pragma unroll
    for (int c = 0; c < 16; c++)
        m = fmaxf(m, g_PART[((size_t)b * 16 + c) * QDIM + tid]);
    xs[tid] = m;
    __syncthreads();

#pragma unroll
    for (int kk = 0; kk < 4; kk++) {
        const int o = tid + kk * 256;
        const float4* w = (const float4*)(W3 + (size_t)o * QDIM);
        float acc = 0.f;
#pragma unroll
        for (int qq = 0; qq < QDIM / 4; qq++) {
            float4 wv = w[qq];
            acc += wv.x * xs[qq * 4 + 0] + wv.y * xs[qq * 4 + 1]
                 + wv.z * xs[qq * 4 + 2] + wv.w * xs[qq * 4 + 3];
        }
        out[(size_t)b * ODIM + o] = fmaxf(acc + b3[o], 0.f);
    }
}

// ============================================================================
extern "C" void kernel_launch(void* const* d_in, const int* in_sizes, int n_in,
                              void* d_out, int out_size)
{
    const float* data = (const float*)d_in[0];
    /* d_in[1] = seq_len: unused by the reference */
    const float* W1 = (const float*)d_in[2];
    const float* b1 = (const float*)d_in[3];
    const float* W2 = (const float*)d_in[4];
    const float* b2 = (const float*)d_in[5];
    const float* W3 = (const float*)d_in[6];
    const float* b3 = (const float*)d_in[7];
    float* out = (float*)d_out;

    float *Q, *K, *SC;
    cudaGetSymbolAddress((void**)&Q,  g_Q);
    cudaGetSymbolAddress((void**)&K,  g_K);
    cudaGetSymbolAddress((void**)&SC, g_SC);

    const size_t strQK = (size_t)SS * QDIM;
    const size_t strSC = (size_t)SS * SS;
    const float  inv_sqrt_qd = 1.0f / 16.0f;   // 1/sqrt(256)

    // 1) Q = data @ W1^T + b1   [65536 x 256]
    mma_gemm<true><<<dim3(QDIM / 128, (BB * SS) / 128, 1), 256>>>(
        data, W1, b1, Q, DD, DD, QDIM, DD, 1.0f, 0, 0, 0);
    // 2) K = data @ W2^T + b2
    mma_gemm<true><<<dim3(QDIM / 128, (BB * SS) / 128, 1), 256>>>(
        data, W2, b2, K, DD, DD, QDIM, DD, 1.0f, 0, 0, 0);

    // 3) scores[b] = (K[b] @ Q[b]^T) / sqrt(QD)   [2048 x 2048] per batch
    mma_gemm<true><<<dim3(SS / 128, SS / 128, BB), 256>>>(
        K, Q, nullptr, SC, QDIM, QDIM, SS, QDIM, inv_sqrt_qd,
        strQK, strQK, strSC);

    // 4) softmax over last dim, in place
    softmax_rows<<<BB * SS, 128>>>(SC);

    // 5) X[b] = attn[b] @ K[b]  (NN: B = K, [k][n] with ldb=QDIM); reuse Q as X
    mma_gemm<false><<<dim3(QDIM / 128, SS / 128, BB), 256>>>(
        SC, K, nullptr, Q, SS, QDIM, QDIM, SS, 1.0f,
        strSC, strQK, strQK);

    // 6) maxpool over sequence (two-stage)
    maxpool_partial<<<dim3(BB, 16), 256>>>(Q);

    // 7) out = relu(xmax @ W3^T + b3)
    final_head<<<BB, 256>>>(W3, b3, out);
}

// round 4
// speedup vs baseline: 1.8359x; 1.1967x over previous
#include <cuda_runtime.h>
#include <cuda_fp16.h>
#include <cstdint>

#define BB  32
#define SS  2048
#define DD  768
#define QDIM 256
#define ODIM 1024

// -------- scratch (allocation-free: __device__ globals) --------
__device__ float g_Q[(size_t)BB * SS * QDIM];      // Q, later reused as X (attn output)
__device__ float g_K[(size_t)BB * SS * QDIM];      // K
__device__ float g_SC[(size_t)BB * SS * SS];       // scores / attn (512 MB)
__device__ float g_PART[BB * 16 * QDIM];           // maxpool partials

__device__ __forceinline__ uint32_t h2pack(float x, float y) {
    __half2 h = __floats2half2_rn(x, y);
    return *(uint32_t*)&h;
}

__device__ __forceinline__ void mma16(float* d, const uint32_t* a, const uint32_t* b) {
    asm volatile(
        "mma.sync.aligned.m16n8k16.row.col.f32.f16.f16.f32 "
        "{%0,%1,%2,%3}, {%4,%5,%6,%7}, {%8,%9}, {%0,%1,%2,%3};"
        : "+f"(d[0]), "+f"(d[1]), "+f"(d[2]), "+f"(d[3])
        : "r"(a[0]), "r"(a[1]), "r"(a[2]), "r"(a[3]), "r"(b[0]), "r"(b[1]));
}

// ============================================================================
// fp16 mma.sync GEMM (fp32 accum), CTA tile 128x128, k-chunk 32, 256 threads
// (8 warps 2x4), warp tile 64x32.
//   BT=true : C[m,n] = scale * sum_k A[m,k]*B[n,k] + bias[n]   (B row-major [N,K])
//   BT=false: C[m,n] = scale * sum_k A[m,k]*B[k,n] + bias[n]   (B row-major [K,N])
// Smem holds packed half2 along k: Xs[k2][row], k2 = k/2. Pad 136 -> k2-stride
// is 8 banks: fragment LDS.32 reads conflict-free.
// Requires M%128==0, N%128==0, kdim%32==0.
// ============================================================================
template <bool BT>
__global__ __launch_bounds__(256) void mma_gemm(
    const float* __restrict__ A, const float* __restrict__ B,
    const float* __restrict__ bias, float* __restrict__ C,
    int lda, int ldb, int ldc, int kdim, float scale,
    size_t sA, size_t sB, size_t sC)
{
    __shared__ uint32_t As[16][136];   // half2-packed, k-major
    __shared__ uint32_t Bs[16][136];

    A += (size_t)blockIdx.z * sA;
    B += (size_t)blockIdx.z * sB;
    C += (size_t)blockIdx.z * sC;
    const int bm = blockIdx.y * 128;
    const int bn = blockIdx.x * 128;

    const int tid  = threadIdx.x;
    const int lane = tid & 31;
    const int wid  = tid >> 5;
    const int wm   = wid & 1;          // warp row (64 m each)
    const int wn   = wid >> 1;         // warp col (32 n each)
    const int qd   = lane >> 2;        // 0..7
    const int cc   = lane & 3;         // 0..3

    // A loader (also B loader for NT): row = tid&127, k-half = (tid>>7)*16
    const int lrow = tid & 127;
    const int lkh  = (tid >> 7) * 16;
    const float* pa   = A + (size_t)(bm + lrow) * lda + lkh;
    const float* pbNT = B + (size_t)(bn + lrow) * ldb + lkh;
    // NN B loader: pair-rows k2 = bk2 + i*8, n = lane*4
    const int bk2 = tid >> 5;          // 0..7
    const int bn4 = lane * 4;
    const float* pbNN = B + (size_t)(bk2 * 2) * ldb + bn + bn4;

    float acc[4][4][4];
#pragma unroll
    for (int i = 0; i < 4; i++)
#pragma unroll
        for (int j = 0; j < 4; j++)
#pragma unroll
            for (int r = 0; r < 4; r++) acc[i][j][r] = 0.f;

    float4 ra[4], rb[4];
    // preload chunk 0
#pragma unroll
    for (int i = 0; i < 4; i++) ra[i] = *(const float4*)(pa + i * 4);
    if (BT) {
#pragma unroll
        for (int i = 0; i < 4; i++) rb[i] = *(const float4*)(pbNT + i * 4);
    } else {
#pragma unroll
        for (int i = 0; i < 2; i++)
#pragma unroll
            for (int j = 0; j < 2; j++)
                rb[2 * i + j] = *(const float4*)(pbNN + (size_t)(i * 16 + j) * ldb);
    }

    const int nc = kdim >> 5;
    for (int ch = 0; ch < nc; ch++) {
        if (ch) __syncthreads();   // previous compute done reading smem

        // store chunk (fp32 -> packed half2 along k)
#pragma unroll
        for (int i = 0; i < 4; i++) {
            const int k2 = (lkh + i * 4) >> 1;
            As[k2 + 0][lrow] = h2pack(ra[i].x, ra[i].y);
            As[k2 + 1][lrow] = h2pack(ra[i].z, ra[i].w);
        }
        if (BT) {
#pragma unroll
            for (int i = 0; i < 4; i++) {
                const int k2 = (lkh + i * 4) >> 1;
                Bs[k2 + 0][lrow] = h2pack(rb[i].x, rb[i].y);
                Bs[k2 + 1][lrow] = h2pack(rb[i].z, rb[i].w);
            }
        } else {
#pragma unroll
            for (int i = 0; i < 2; i++) {
                uint4 v;
                v.x = h2pack(rb[2 * i].x, rb[2 * i + 1].x);
                v.y = h2pack(rb[2 * i].y, rb[2 * i + 1].y);
                v.z = h2pack(rb[2 * i].z, rb[2 * i + 1].z);
                v.w = h2pack(rb[2 * i].w, rb[2 * i + 1].w);
                *(uint4*)&Bs[bk2 + i * 8][bn4] = v;
            }
        }
        __syncthreads();

        // prefetch next chunk into registers (hidden under compute)
        if (ch + 1 < nc) {
            const int k0 = (ch + 1) << 5;
#pragma unroll
            for (int i = 0; i < 4; i++) ra[i] = *(const float4*)(pa + k0 + i * 4);
            if (BT) {
#pragma unroll
                for (int i = 0; i < 4; i++) rb[i] = *(const float4*)(pbNT + k0 + i * 4);
            } else {
#pragma unroll
                for (int i = 0; i < 2; i++)
#pragma unroll
                    for (int j = 0; j < 2; j++)
                        rb[2 * i + j] = *(const float4*)(pbNN + (size_t)(k0 + i * 16 + j) * ldb);
            }
        }

        // compute 2 k-slices of 16
#pragma unroll
        for (int ks = 0; ks < 2; ks++) {
            const int kb = ks * 8 + cc;
            uint32_t af[4][4], bf[4][2];
#pragma unroll
            for (int mt = 0; mt < 4; mt++) {
                const int m = wm * 64 + mt * 16 + qd;
                af[mt][0] = As[kb][m];
                af[mt][1] = As[kb][m + 8];
                af[mt][2] = As[kb + 4][m];
                af[mt][3] = As[kb + 4][m + 8];
            }
#pragma unroll
            for (int nt = 0; nt < 4; nt++) {
                const int n = wn * 32 + nt * 8 + qd;
                bf[nt][0] = Bs[kb][n];
                bf[nt][1] = Bs[kb + 4][n];
            }
#pragma unroll
            for (int mt = 0; mt < 4; mt++)
#pragma unroll
                for (int nt = 0; nt < 4; nt++)
                    mma16(acc[mt][nt], af[mt], bf[nt]);
        }
    }

    // epilogue: scale + optional bias, float2 stores
#pragma unroll
    for (int mt = 0; mt < 4; mt++) {
        const int m0 = bm + wm * 64 + mt * 16 + qd;
#pragma unroll
        for (int nt = 0; nt < 4; nt++) {
            const int n = bn + wn * 32 + nt * 8 + cc * 2;
            float bx = 0.f, by = 0.f;
            if (bias) { bx = bias[n]; by = bias[n + 1]; }
            float2 v0, v1;
            v0.x = acc[mt][nt][0] * scale + bx;
            v0.y = acc[mt][nt][1] * scale + by;
            v1.x = acc[mt][nt][2] * scale + bx;
            v1.y = acc[mt][nt][3] * scale + by;
            *(float2*)(C + (size_t)m0 * ldc + n)       = v0;
            *(float2*)(C + (size_t)(m0 + 8) * ldc + n) = v1;
        }
    }
}

// ============================================================================
// Row softmax over S=2048, one CTA (128 threads) per row, row kept in regs.
// ============================================================================
__global__ __launch_bounds__(128) void softmax_rows(float* __restrict__ sc)
{
    float* p = sc + (size_t)blockIdx.x * SS;
    const int tid = threadIdx.x;

    float v[16];
    float m = -INFINITY;
#pragma unroll
    for (int i = 0; i < 16; i++) { v[i] = p[tid + i * 128]; m = fmaxf(m, v[i]); }

    __shared__ float redm[4];
#pragma unroll
    for (int o = 16; o > 0; o >>= 1) m = fmaxf(m, __shfl_xor_sync(0xffffffffu, m, o));
    if ((tid & 31) == 0) redm[tid >> 5] = m;
    __syncthreads();
    m = fmaxf(fmaxf(redm[0], redm[1]), fmaxf(redm[2], redm[3]));

    float s = 0.f;
#pragma unroll
    for (int i = 0; i < 16; i++) { v[i] = __expf(v[i] - m); s += v[i]; }

    __shared__ float reds[4];
#pragma unroll
    for (int o = 16; o > 0; o >>= 1) s += __shfl_xor_sync(0xffffffffu, s, o);
    if ((tid & 31) == 0) reds[tid >> 5] = s;
    __syncthreads();
    s = (reds[0] + reds[1]) + (reds[2] + reds[3]);

    const float inv = 1.f / s;
#pragma unroll
    for (int i = 0; i < 16; i++) p[tid + i * 128] = v[i] * inv;
}

// ============================================================================
__global__ __launch_bounds__(256) void maxpool_partial(const float* __restrict__ X)
{
    const int b = blockIdx.x;
    const int c = blockIdx.y;
    const float* p = X + ((size_t)b * SS + (size_t)c * 128) * QDIM + threadIdx.x;
    float m = -INFINITY;
#pragma unroll 8
    for (int s = 0; s < 128; s++) m = fmaxf(m, p[(size_t)s * QDIM]);
    g_PART[((size_t)b * 16 + c) * QDIM + threadIdx.x] = m;
}

__global__ __launch_bounds__(256) void final_head(
    const float* __restrict__ W3, const float* __restrict__ b3,
    float* __restrict__ out)
{
    const int b = blockIdx.x;
    const int tid = threadIdx.x;
    __shared__ float xs[QDIM];

    float m = -INFINITY;
#pragma unroll
    for (int c = 0; c < 16; c++)
        m = fmaxf(m, g_PART[((size_t)b * 16 + c) * QDIM + tid]);
    xs[tid] = m;
    __syncthreads();

#pragma unroll
    for (int kk = 0; kk < 4; kk++) {
        const int o = tid + kk * 256;
        const float4* w = (const float4*)(W3 + (size_t)o * QDIM);
        float acc = 0.f;
#pragma unroll
        for (int qq = 0; qq < QDIM / 4; qq++) {
            float4 wv = w[qq];
            acc += wv.x * xs[qq * 4 + 0] + wv.y * xs[qq * 4 + 1]
                 + wv.z * xs[qq * 4 + 2] + wv.w * xs[qq * 4 + 3];
        }
        out[(size_t)b * ODIM + o] = fmaxf(acc + b3[o], 0.f);
    }
}

// ============================================================================
extern "C" void kernel_launch(void* const* d_in, const int* in_sizes, int n_in,
                              void* d_out, int out_size)
{
    const float* data = (const float*)d_in[0];
    /* d_in[1] = seq_len: unused by the reference */
    const float* W1 = (const float*)d_in[2];
    const float* b1 = (const float*)d_in[3];
    const float* W2 = (const float*)d_in[4];
    const float* b2 = (const float*)d_in[5];
    const float* W3 = (const float*)d_in[6];
    const float* b3 = (const float*)d_in[7];
    float* out = (float*)d_out;

    float *Q, *K, *SC;
    cudaGetSymbolAddress((void**)&Q,  g_Q);
    cudaGetSymbolAddress((void**)&K,  g_K);
    cudaGetSymbolAddress((void**)&SC, g_SC);

    const size_t strQK = (size_t)SS * QDIM;
    const size_t strSC = (size_t)SS * SS;
    const float  inv_sqrt_qd = 1.0f / 16.0f;   // 1/sqrt(256)

    // 1) Q = data @ W1^T + b1   [65536 x 256]
    mma_gemm<true><<<dim3(QDIM / 128, (BB * SS) / 128, 1), 256>>>(
        data, W1, b1, Q, DD, DD, QDIM, DD, 1.0f, 0, 0, 0);
    // 2) K = data @ W2^T + b2
    mma_gemm<true><<<dim3(QDIM / 128, (BB * SS) / 128, 1), 256>>>(
        data, W2, b2, K, DD, DD, QDIM, DD, 1.0f, 0, 0, 0);

    // 3) scores[b] = (K[b] @ Q[b]^T) / sqrt(QD)   [2048 x 2048] per batch
    mma_gemm<true><<<dim3(SS / 128, SS / 128, BB), 256>>>(
        K, Q, nullptr, SC, QDIM, QDIM, SS, QDIM, inv_sqrt_qd,
        strQK, strQK, strSC);

    // 4) softmax over last dim, in place
    softmax_rows<<<BB * SS, 128>>>(SC);

    // 5) X[b] = attn[b] @ K[b]  (NN: B = K, [k][n] with ldb=QDIM); reuse Q as X
    mma_gemm<false><<<dim3(QDIM / 128, SS / 128, BB), 256>>>(
        SC, K, nullptr, Q, SS, QDIM, QDIM, SS, 1.0f,
        strSC, strQK, strQK);

    // 6) maxpool over sequence (two-stage)
    maxpool_partial<<<dim3(BB, 16), 256>>>(Q);

    // 7) out = relu(xmax @ W3^T + b3)
    final_head<<<BB, 256>>>(W3, b3, out);
}

// round 5
// speedup vs baseline: 4.1979x; 2.2866x over previous
#include <cuda_runtime.h>
#include <cuda_fp16.h>
#include <cstdint>

#define BB  32
#define SS  2048
#define DD  768
#define QDIM 256
#define ODIM 1024
#define STAGES 4

// -------- scratch (allocation-free: __device__ globals) --------
__device__ __half g_dataH[(size_t)BB * SS * DD];
__device__ __half g_W1h[QDIM * DD];
__device__ __half g_W2h[QDIM * DD];
__device__ __half g_Qh [(size_t)BB * SS * QDIM];
__device__ __half g_Kh [(size_t)BB * SS * QDIM];
__device__ __half g_KTh[(size_t)BB * QDIM * SS];   // K transposed [b][q][s]
__device__ float  g_SC [(size_t)BB * SS * SS];     // scores fp32 (512 MB)
__device__ __half g_AH [(size_t)BB * SS * SS];     // attn probs fp16 (256 MB)
__device__ float  g_XT [(size_t)BB * QDIM * SS];   // attn out transposed [b][q][s]
__device__ float  g_XMAX[BB * QDIM];

__device__ __forceinline__ uint32_t smem_u32(const void* p) {
    uint32_t a;
    asm("{ .reg .u64 t; cvta.to.shared.u64 t, %1; cvt.u32.u64 %0, t; }" : "=r"(a) : "l"(p));
    return a;
}
__device__ __forceinline__ void cp16(uint32_t dst, const void* src) {
    asm volatile("cp.async.cg.shared.global [%0], [%1], 16;" :: "r"(dst), "l"(src));
}
#define CP_COMMIT() asm volatile("cp.async.commit_group;" ::: "memory")
#define CP_WAIT(n)  asm volatile("cp.async.wait_group %0;" :: "n"(n) : "memory")
#define LDS32(v, a) asm volatile("ld.shared.b32 %0, [%1];" : "=r"(v) : "r"(a))

__device__ __forceinline__ void mma16(float* d, const uint32_t* a, const uint32_t* b) {
    asm volatile(
        "mma.sync.aligned.m16n8k16.row.col.f32.f16.f16.f32 "
        "{%0,%1,%2,%3}, {%4,%5,%6,%7}, {%8,%9}, {%0,%1,%2,%3};"
        : "+f"(d[0]), "+f"(d[1]), "+f"(d[2]), "+f"(d[3])
        : "r"(a[0]), "r"(a[1]), "r"(a[2]), "r"(a[3]), "r"(b[0]), "r"(b[1]));
}

// ============================================================================
// fp16 NT GEMM, cp.async 4-stage pipeline. CTA 128x128, k-chunk 32, 256 thr
// (8 warps 2x4), warp tile 64x32. A [M,K], B [N,K] both fp16 row-major.
//   EPI=0: C fp32, *scale
//   EPI=1: C fp16, *scale + bias
//   EPI=2: C fp16 + bias, ALSO CT fp16 transposed per-batch [QDIM][SS] (proj-K)
// Smem rows padded to 40 halves (20 banks): conflict-free LDS32 + cp.async.
// Requires M%128==0, N%128==0, kdim%32==0.
// ============================================================================
template <int EPI>
__global__ __launch_bounds__(256, 2) void hgemm(
    const __half* __restrict__ A, const __half* __restrict__ B,
    const float* __restrict__ bias, void* __restrict__ Cv,
    __half* __restrict__ CT,
    int lda, int ldb, int ldc, int kdim, float scale,
    size_t sA, size_t sB, size_t sC)
{
    extern __shared__ __half sm[];
    A += (size_t)blockIdx.z * sA;
    B += (size_t)blockIdx.z * sB;
    const int bm = blockIdx.y * 128;
    const int bn = blockIdx.x * 128;

    const int tid = threadIdx.x;
    const int lane = tid & 31, wid = tid >> 5;
    const int wm = wid & 1, wn = wid >> 1;      // warp 64m x 32n
    const int qd = lane >> 2, cc = lane & 3;

    // loader: thread covers row = tid>>1, halves [seg, seg+16)
    const int lrow = tid >> 1;
    const int lseg = (tid & 1) * 16;
    const __half* pa = A + (size_t)(bm + lrow) * lda + lseg;
    const __half* pb = B + (size_t)(bn + lrow) * ldb + lseg;
    const uint32_t smb = smem_u32(sm);
    const uint32_t dA = smb + (uint32_t)(lrow * 40 + lseg) * 2;
    const uint32_t dB = dA + 5120 * 2;
    const uint32_t STG = 10240 * 2;             // bytes per stage (A+B)

    float acc[4][4][4];
#pragma unroll
    for (int i = 0; i < 4; i++)
#pragma unroll
        for (int j = 0; j < 4; j++)
#pragma unroll
            for (int r = 0; r < 4; r++) acc[i][j][r] = 0.f;

    const int nc = kdim >> 5;

    // prologue: stages 0..STAGES-2
#pragma unroll
    for (int s = 0; s < STAGES - 1; s++) {
        if (s < nc) {
            const size_t k0 = (size_t)s * 32;
            const uint32_t da = dA + s * STG, db = dB + s * STG;
            cp16(da,      pa + k0);
            cp16(da + 16, pa + k0 + 8);
            cp16(db,      pb + k0);
            cp16(db + 16, pb + k0 + 8);
        }
        CP_COMMIT();
    }

    for (int ch = 0; ch < nc; ch++) {
        CP_WAIT(STAGES - 2);
        __syncthreads();   // stage ch ready; everyone done reading stage ch-1

        // refill the stage freed by chunk ch-1
        {
            const int nxt = ch + STAGES - 1;
            if (nxt < nc) {
                const int st = nxt & (STAGES - 1);
                const size_t k0 = (size_t)nxt * 32;
                const uint32_t da = dA + st * STG, db = dB + st * STG;
                cp16(da,      pa + k0);
                cp16(da + 16, pa + k0 + 8);
                cp16(db,      pb + k0);
                cp16(db + 16, pb + k0 + 8);
            }
            CP_COMMIT();
        }

        const uint32_t sa = smb + (uint32_t)(ch & (STAGES - 1)) * STG;
        const uint32_t sb = sa + 5120 * 2;
#pragma unroll
        for (int ks = 0; ks < 2; ks++) {
            uint32_t af[4][4], bf[4][2];
#pragma unroll
            for (int mt = 0; mt < 4; mt++) {
                const uint32_t base =
                    sa + (uint32_t)((wm * 64 + mt * 16 + qd) * 40 + ks * 16 + cc * 2) * 2;
                LDS32(af[mt][0], base);
                LDS32(af[mt][1], base + 640);        // +8 rows
                LDS32(af[mt][2], base + 16);         // +8 k
                LDS32(af[mt][3], base + 656);
            }
#pragma unroll
            for (int nt = 0; nt < 4; nt++) {
                const uint32_t base =
                    sb + (uint32_t)((wn * 32 + nt * 8 + qd) * 40 + ks * 16 + cc * 2) * 2;
                LDS32(bf[nt][0], base);
                LDS32(bf[nt][1], base + 16);
            }
#pragma unroll
            for (int mt = 0; mt < 4; mt++)
#pragma unroll
                for (int nt = 0; nt < 4; nt++)
                    mma16(acc[mt][nt], af[mt], bf[nt]);
        }
    }

    // ---- epilogue ----
#pragma unroll
    for (int mt = 0; mt < 4; mt++) {
        const int m0 = bm + wm * 64 + mt * 16 + qd;
#pragma unroll
        for (int nt = 0; nt < 4; nt++) {
            const int n0 = bn + wn * 32 + nt * 8 + cc * 2;
            float c0 = acc[mt][nt][0] * scale;
            float c1 = acc[mt][nt][1] * scale;
            float c2 = acc[mt][nt][2] * scale;
            float c3 = acc[mt][nt][3] * scale;
            if (EPI == 0) {
                float* Cf = (float*)Cv + (size_t)blockIdx.z * sC;
                *(float2*)(Cf + (size_t)m0 * ldc + n0)       = make_float2(c0, c1);
                *(float2*)(Cf + (size_t)(m0 + 8) * ldc + n0) = make_float2(c2, c3);
            } else {
                const float bx = bias[n0], by = bias[n0 + 1];
                c0 += bx; c1 += by; c2 += bx; c3 += by;
                __half2 h0 = __floats2half2_rn(c0, c1);
                __half2 h1 = __floats2half2_rn(c2, c3);
                __half* Ch = (__half*)Cv + (size_t)blockIdx.z * sC;
                *(__half2*)(Ch + (size_t)m0 * ldc + n0)       = h0;
                *(__half2*)(Ch + (size_t)(m0 + 8) * ldc + n0) = h1;
                if (EPI == 2) {
                    const int b0 = m0 >> 11, s0 = m0 & (SS - 1);
                    __half* t = CT + ((size_t)b0 * QDIM + n0) * SS + s0;
                    t[0]      = __low2half(h0);
                    t[SS]     = __high2half(h0);
                    t[8]      = __low2half(h1);
                    t[SS + 8] = __high2half(h1);
                }
            }
        }
    }
}

// ============================================================================
// fp32 -> fp16 conversion (n % 8 == 0)
// ============================================================================
__global__ __launch_bounds__(256) void f2h_kernel(
    const float* __restrict__ s, __half* __restrict__ d, size_t n)
{
    const size_t i = ((size_t)blockIdx.x * 256 + threadIdx.x) * 8;
    if (i + 8 <= n) {
        float4 a = *(const float4*)(s + i);
        float4 b = *(const float4*)(s + i + 4);
        uint4 o;
        __half2 h;
        h = __floats2half2_rn(a.x, a.y); o.x = *(uint32_t*)&h;
        h = __floats2half2_rn(a.z, a.w); o.y = *(uint32_t*)&h;
        h = __floats2half2_rn(b.x, b.y); o.z = *(uint32_t*)&h;
        h = __floats2half2_rn(b.z, b.w); o.w = *(uint32_t*)&h;
        *(uint4*)(d + i) = o;
    }
}

// ============================================================================
// Row softmax over S=2048: fp32 scores in, fp16 probs out.
// ============================================================================
__global__ __launch_bounds__(128) void softmax_rows(
    const float* __restrict__ sc, __half* __restrict__ ah)
{
    const float* p = sc + (size_t)blockIdx.x * SS;
    __half* q = ah + (size_t)blockIdx.x * SS;
    const int tid = threadIdx.x;

    float v[16];
    float m = -INFINITY;
#pragma unroll
    for (int i = 0; i < 16; i++) { v[i] = p[tid + i * 128]; m = fmaxf(m, v[i]); }

    __shared__ float redm[4];
#pragma unroll
    for (int o = 16; o > 0; o >>= 1) m = fmaxf(m, __shfl_xor_sync(0xffffffffu, m, o));
    if ((tid & 31) == 0) redm[tid >> 5] = m;
    __syncthreads();
    m = fmaxf(fmaxf(redm[0], redm[1]), fmaxf(redm[2], redm[3]));

    float s = 0.f;
#pragma unroll
    for (int i = 0; i < 16; i++) { v[i] = __expf(v[i] - m); s += v[i]; }

    __shared__ float reds[4];
#pragma unroll
    for (int o = 16; o > 0; o >>= 1) s += __shfl_xor_sync(0xffffffffu, s, o);
    if ((tid & 31) == 0) reds[tid >> 5] = s;
    __syncthreads();
    s = (reds[0] + reds[1]) + (reds[2] + reds[3]);

    const float inv = 1.f / s;
#pragma unroll
    for (int i = 0; i < 16; i++) q[tid + i * 128] = __float2half(v[i] * inv);
}

// ============================================================================
// Contiguous row max over XT[b][q][0:2048] -> g_XMAX  (one warp per row)
// ============================================================================
__global__ __launch_bounds__(256) void maxpool_rows(const float* __restrict__ XT)
{
    const int r = blockIdx.x * 8 + (threadIdx.x >> 5);
    const int lane = threadIdx.x & 31;
    const float4* p = (const float4*)(XT + (size_t)r * SS);
    float m = -INFINITY;
#pragma unroll
    for (int i = 0; i < 16; i++) {
        float4 v = p[lane + i * 32];
        m = fmaxf(m, fmaxf(fmaxf(v.x, v.y), fmaxf(v.z, v.w)));
    }
#pragma unroll
    for (int o = 16; o > 0; o >>= 1) m = fmaxf(m, __shfl_xor_sync(0xffffffffu, m, o));
    if (lane == 0) g_XMAX[r] = m;
}

// ============================================================================
__global__ __launch_bounds__(256) void final_head(
    const float* __restrict__ W3, const float* __restrict__ b3,
    float* __restrict__ out)
{
    const int b = blockIdx.x;
    const int tid = threadIdx.x;
    __shared__ float xs[QDIM];
    xs[tid] = g_XMAX[b * QDIM + tid];
    __syncthreads();

#pragma unroll
    for (int kk = 0; kk < 4; kk++) {
        const int o = tid + kk * 256;
        const float4* w = (const float4*)(W3 + (size_t)o * QDIM);
        float acc = 0.f;
#pragma unroll
        for (int qq = 0; qq < QDIM / 4; qq++) {
            float4 wv = w[qq];
            acc += wv.x * xs[qq * 4 + 0] + wv.y * xs[qq * 4 + 1]
                 + wv.z * xs[qq * 4 + 2] + wv.w * xs[qq * 4 + 3];
        }
        out[(size_t)b * ODIM + o] = fmaxf(acc + b3[o], 0.f);
    }
}

// ============================================================================
extern "C" void kernel_launch(void* const* d_in, const int* in_sizes, int n_in,
                              void* d_out, int out_size)
{
    const float* data = (const float*)d_in[0];
    /* d_in[1] = seq_len: unused by the reference */
    const float* W1 = (const float*)d_in[2];
    const float* b1 = (const float*)d_in[3];
    const float* W2 = (const float*)d_in[4];
    const float* b2 = (const float*)d_in[5];
    const float* W3 = (const float*)d_in[6];
    const float* b3 = (const float*)d_in[7];
    float* out = (float*)d_out;

    __half *dataH, *W1h, *W2h, *Qh, *Kh, *KTh, *AH;
    float *SC, *XT;
    cudaGetSymbolAddress((void**)&dataH, g_dataH);
    cudaGetSymbolAddress((void**)&W1h, g_W1h);
    cudaGetSymbolAddress((void**)&W2h, g_W2h);
    cudaGetSymbolAddress((void**)&Qh,  g_Qh);
    cudaGetSymbolAddress((void**)&Kh,  g_Kh);
    cudaGetSymbolAddress((void**)&KTh, g_KTh);
    cudaGetSymbolAddress((void**)&SC,  g_SC);
    cudaGetSymbolAddress((void**)&AH,  g_AH);
    cudaGetSymbolAddress((void**)&XT,  g_XT);

    const int SMEM = STAGES * 10240 * 2;   // 81920 B
    cudaFuncSetAttribute(hgemm<0>, cudaFuncAttributeMaxDynamicSharedMemorySize, SMEM);
    cudaFuncSetAttribute(hgemm<1>, cudaFuncAttributeMaxDynamicSharedMemorySize, SMEM);
    cudaFuncSetAttribute(hgemm<2>, cudaFuncAttributeMaxDynamicSharedMemorySize, SMEM);

    const size_t strQK = (size_t)SS * QDIM;
    const size_t strSC = (size_t)SS * SS;
    const float  inv_sqrt_qd = 1.0f / 16.0f;

    // 0) convert inputs to fp16
    const size_t nd = (size_t)BB * SS * DD;
    f2h_kernel<<<(unsigned)(nd / (256 * 8)), 256>>>(data, dataH, nd);
    f2h_kernel<<<(QDIM * DD) / (256 * 8), 256>>>(W1, W1h, QDIM * DD);
    f2h_kernel<<<(QDIM * DD) / (256 * 8), 256>>>(W2, W2h, QDIM * DD);

    // 1) Q = data @ W1^T + b1 -> fp16
    hgemm<1><<<dim3(QDIM / 128, (BB * SS) / 128, 1), 256, SMEM>>>(
        dataH, W1h, b1, Qh, nullptr, DD, DD, QDIM, DD, 1.0f, 0, 0, 0);
    // 2) K = data @ W2^T + b2 -> fp16 + fp16 transposed
    hgemm<2><<<dim3(QDIM / 128, (BB * SS) / 128, 1), 256, SMEM>>>(
        dataH, W2h, b2, Kh, KTh, DD, DD, QDIM, DD, 1.0f, 0, 0, 0);

    // 3) scores[b] = (K[b] @ Q[b]^T) / 16 -> fp32
    hgemm<0><<<dim3(SS / 128, SS / 128, BB), 256, SMEM>>>(
        Kh, Qh, nullptr, SC, nullptr, QDIM, QDIM, SS, QDIM, inv_sqrt_qd,
        strQK, strQK, strSC);

    // 4) softmax -> fp16 probs
    softmax_rows<<<BB * SS, 128>>>(SC, AH);

    // 5) XT[b][q][s] = sum_j KT[b][q][j] * attn[b][s][j]  (NT, fp32 out)
    hgemm<0><<<dim3(SS / 128, QDIM / 128, BB), 256, SMEM>>>(
        KTh, AH, nullptr, XT, nullptr, SS, SS, SS, SS, 1.0f,
        strQK, strSC, strQK);

    // 6) maxpool over contiguous s
    maxpool_rows<<<BB * QDIM / 8, 256>>>(XT);

    // 7) out = relu(xmax @ W3^T + b3)
    final_head<<<BB, 256>>>(W3, b3, out);
}

// round 6
// speedup vs baseline: 4.8201x; 1.1482x over previous
#include <cuda_runtime.h>
#include <cuda_fp16.h>
#include <cstdint>

#define BB  32
#define SS  2048
#define DD  768
#define QDIM 256
#define ODIM 1024
#define STAGES 4

// -------- scratch (allocation-free: __device__ globals) --------
__device__ __half g_dataH[(size_t)BB * SS * DD];
__device__ __half g_W1h[QDIM * DD];
__device__ __half g_W2h[QDIM * DD];
__device__ __half g_Qh [(size_t)BB * SS * QDIM];
__device__ __half g_Kh [(size_t)BB * SS * QDIM];
__device__ __half g_KTh[(size_t)BB * QDIM * SS];   // K transposed [b][q][s]
__device__ float  g_SC [(size_t)BB * SS * SS];     // scores fp32 (512 MB)
__device__ __half g_AH [(size_t)BB * SS * SS];     // attn probs fp16 (256 MB)
__device__ float  g_XT [(size_t)BB * QDIM * SS];   // attn out transposed [b][q][s]
__device__ float  g_XMAX[BB * QDIM];

__device__ __forceinline__ uint32_t smem_u32(const void* p) {
    uint32_t a;
    asm("{ .reg .u64 t; cvta.to.shared.u64 t, %1; cvt.u32.u64 %0, t; }" : "=r"(a) : "l"(p));
    return a;
}
__device__ __forceinline__ void cp16(uint32_t dst, const void* src) {
    asm volatile("cp.async.cg.shared.global [%0], [%1], 16;" :: "r"(dst), "l"(src));
}
#define CP_COMMIT() asm volatile("cp.async.commit_group;" ::: "memory")
#define CP_WAIT(n)  asm volatile("cp.async.wait_group %0;" :: "n"(n) : "memory")

__device__ __forceinline__ void ldsm4(uint32_t& r0, uint32_t& r1, uint32_t& r2,
                                      uint32_t& r3, uint32_t addr) {
    asm volatile("ldmatrix.sync.aligned.m8n8.x4.shared.b16 {%0,%1,%2,%3}, [%4];"
                 : "=r"(r0), "=r"(r1), "=r"(r2), "=r"(r3) : "r"(addr));
}

__device__ __forceinline__ void mma16(float* d, const uint32_t* a, const uint32_t* b) {
    asm volatile(
        "mma.sync.aligned.m16n8k16.row.col.f32.f16.f16.f32 "
        "{%0,%1,%2,%3}, {%4,%5,%6,%7}, {%8,%9}, {%0,%1,%2,%3};"
        : "+f"(d[0]), "+f"(d[1]), "+f"(d[2]), "+f"(d[3])
        : "r"(a[0]), "r"(a[1]), "r"(a[2]), "r"(a[3]), "r"(b[0]), "r"(b[1]));
}

// ============================================================================
// fp16 NT GEMM, cp.async 4-stage pipeline + ldmatrix fragment loads.
// CTA 128x128, k-chunk 32, 256 thr (8 warps 2x4), warp tile 64x32.
// A [M,K], B [N,K] fp16 row-major.
//   EPI=0: C fp32, *scale
//   EPI=1: C fp16, *scale + bias
//   EPI=2: C fp16 + bias, ALSO CT fp16 transposed per-batch [QDIM][SS] (proj-K)
// Smem rows padded to 40 halves (80B): ldmatrix row banks {0,20,8,28,16,4,24,12}
// -> conflict-free. Requires M%128==0, N%128==0, kdim%32==0.
// ============================================================================
template <int EPI>
__global__ __launch_bounds__(256, 2) void hgemm(
    const __half* __restrict__ A, const __half* __restrict__ B,
    const float* __restrict__ bias, void* __restrict__ Cv,
    __half* __restrict__ CT,
    int lda, int ldb, int ldc, int kdim, float scale,
    size_t sA, size_t sB, size_t sC)
{
    extern __shared__ __half sm[];
    A += (size_t)blockIdx.z * sA;
    B += (size_t)blockIdx.z * sB;
    const int bm = blockIdx.y * 128;
    const int bn = blockIdx.x * 128;

    const int tid = threadIdx.x;
    const int lane = tid & 31, wid = tid >> 5;
    const int wm = wid & 1, wn = wid >> 1;      // warp 64m x 32n
    const int qd = lane >> 2, cc = lane & 3;

    // loader: thread covers row = tid>>1, halves [seg, seg+16)
    const int lrow = tid >> 1;
    const int lseg = (tid & 1) * 16;
    const __half* pa = A + (size_t)(bm + lrow) * lda + lseg;
    const __half* pb = B + (size_t)(bn + lrow) * ldb + lseg;
    const uint32_t smb = smem_u32(sm);
    const uint32_t dA = smb + (uint32_t)(lrow * 40 + lseg) * 2;
    const uint32_t dB = dA + 5120 * 2;
    const uint32_t STG = 10240 * 2;             // bytes per stage (A+B)

    // ldmatrix per-lane offsets (relative to stage base, ks=0)
    uint32_t aoff[4], boff[2];
#pragma unroll
    for (int mt = 0; mt < 4; mt++)
        aoff[mt] = (uint32_t)(((wm * 64 + mt * 16 + (lane & 7) + (lane & 8)) * 40
                               + ((lane >> 4) * 8)) * 2);
#pragma unroll
    for (int np = 0; np < 2; np++)
        boff[np] = (uint32_t)(5120 * 2
                   + ((wn * 32 + np * 16 + (lane & 7) + ((lane >> 4) * 8)) * 40
                      + (lane & 8)) * 2);

    float acc[4][4][4];
#pragma unroll
    for (int i = 0; i < 4; i++)
#pragma unroll
        for (int j = 0; j < 4; j++)
#pragma unroll
            for (int r = 0; r < 4; r++) acc[i][j][r] = 0.f;

    const int nc = kdim >> 5;

    // prologue: stages 0..STAGES-2
#pragma unroll
    for (int s = 0; s < STAGES - 1; s++) {
        if (s < nc) {
            const size_t k0 = (size_t)s * 32;
            const uint32_t da = dA + s * STG, db = dB + s * STG;
            cp16(da,      pa + k0);
            cp16(da + 16, pa + k0 + 8);
            cp16(db,      pb + k0);
            cp16(db + 16, pb + k0 + 8);
        }
        CP_COMMIT();
    }

    for (int ch = 0; ch < nc; ch++) {
        CP_WAIT(STAGES - 2);
        __syncthreads();   // stage ch ready; everyone done reading stage ch-1

        // refill the stage freed by chunk ch-1
        {
            const int nxt = ch + STAGES - 1;
            if (nxt < nc) {
                const int st = nxt & (STAGES - 1);
                const size_t k0 = (size_t)nxt * 32;
                const uint32_t da = dA + st * STG, db = dB + st * STG;
                cp16(da,      pa + k0);
                cp16(da + 16, pa + k0 + 8);
                cp16(db,      pb + k0);
                cp16(db + 16, pb + k0 + 8);
            }
            CP_COMMIT();
        }

        const uint32_t sa = smb + (uint32_t)(ch & (STAGES - 1)) * STG;
#pragma unroll
        for (int ks = 0; ks < 2; ks++) {
            uint32_t af[4][4], bf[4][2];
#pragma unroll
            for (int mt = 0; mt < 4; mt++)
                ldsm4(af[mt][0], af[mt][1], af[mt][2], af[mt][3],
                      sa + aoff[mt] + ks * 32);
#pragma unroll
            for (int np = 0; np < 2; np++)
                ldsm4(bf[2 * np][0], bf[2 * np][1], bf[2 * np + 1][0],
                      bf[2 * np + 1][1], sa + boff[np] + ks * 32);
#pragma unroll
            for (int mt = 0; mt < 4; mt++)
#pragma unroll
                for (int nt = 0; nt < 4; nt++)
                    mma16(acc[mt][nt], af[mt], bf[nt]);
        }
    }

    // ---- epilogue ----
#pragma unroll
    for (int mt = 0; mt < 4; mt++) {
        const int m0 = bm + wm * 64 + mt * 16 + qd;
#pragma unroll
        for (int nt = 0; nt < 4; nt++) {
            const int n0 = bn + wn * 32 + nt * 8 + cc * 2;
            float c0 = acc[mt][nt][0] * scale;
            float c1 = acc[mt][nt][1] * scale;
            float c2 = acc[mt][nt][2] * scale;
            float c3 = acc[mt][nt][3] * scale;
            if (EPI == 0) {
                float* Cf = (float*)Cv + (size_t)blockIdx.z * sC;
                *(float2*)(Cf + (size_t)m0 * ldc + n0)       = make_float2(c0, c1);
                *(float2*)(Cf + (size_t)(m0 + 8) * ldc + n0) = make_float2(c2, c3);
            } else {
                const float bx = bias[n0], by = bias[n0 + 1];
                c0 += bx; c1 += by; c2 += bx; c3 += by;
                __half2 h0 = __floats2half2_rn(c0, c1);
                __half2 h1 = __floats2half2_rn(c2, c3);
                __half* Ch = (__half*)Cv + (size_t)blockIdx.z * sC;
                *(__half2*)(Ch + (size_t)m0 * ldc + n0)       = h0;
                *(__half2*)(Ch + (size_t)(m0 + 8) * ldc + n0) = h1;
                if (EPI == 2) {
                    const int b0 = m0 >> 11, s0 = m0 & (SS - 1);
                    __half* t = CT + ((size_t)b0 * QDIM + n0) * SS + s0;
                    t[0]      = __low2half(h0);
                    t[SS]     = __high2half(h0);
                    t[8]      = __low2half(h1);
                    t[SS + 8] = __high2half(h1);
                }
            }
        }
    }
}

// ============================================================================
// fp32 -> fp16 conversion (n % 8 == 0)
// ============================================================================
__global__ __launch_bounds__(256) void f2h_kernel(
    const float* __restrict__ s, __half* __restrict__ d, size_t n)
{
    const size_t i = ((size_t)blockIdx.x * 256 + threadIdx.x) * 8;
    if (i + 8 <= n) {
        float4 a = *(const float4*)(s + i);
        float4 b = *(const float4*)(s + i + 4);
        uint4 o;
        __half2 h;
        h = __floats2half2_rn(a.x, a.y); o.x = *(uint32_t*)&h;
        h = __floats2half2_rn(a.z, a.w); o.y = *(uint32_t*)&h;
        h = __floats2half2_rn(b.x, b.y); o.z = *(uint32_t*)&h;
        h = __floats2half2_rn(b.z, b.w); o.w = *(uint32_t*)&h;
        *(uint4*)(d + i) = o;
    }
}

// ============================================================================
// Row softmax over S=2048: fp32 scores in, fp16 probs out.
// ============================================================================
__global__ __launch_bounds__(128) void softmax_rows(
    const float* __restrict__ sc, __half* __restrict__ ah)
{
    const float* p = sc + (size_t)blockIdx.x * SS;
    __half* q = ah + (size_t)blockIdx.x * SS;
    const int tid = threadIdx.x;

    float v[16];
    float m = -INFINITY;
#pragma unroll
    for (int i = 0; i < 16; i++) { v[i] = p[tid + i * 128]; m = fmaxf(m, v[i]); }

    __shared__ float redm[4];
#pragma unroll
    for (int o = 16; o > 0; o >>= 1) m = fmaxf(m, __shfl_xor_sync(0xffffffffu, m, o));
    if ((tid & 31) == 0) redm[tid >> 5] = m;
    __syncthreads();
    m = fmaxf(fmaxf(redm[0], redm[1]), fmaxf(redm[2], redm[3]));

    float s = 0.f;
#pragma unroll
    for (int i = 0; i < 16; i++) { v[i] = __expf(v[i] - m); s += v[i]; }

    __shared__ float reds[4];
#pragma unroll
    for (int o = 16; o > 0; o >>= 1) s += __shfl_xor_sync(0xffffffffu, s, o);
    if ((tid & 31) == 0) reds[tid >> 5] = s;
    __syncthreads();
    s = (reds[0] + reds[1]) + (reds[2] + reds[3]);

    const float inv = 1.f / s;
#pragma unroll
    for (int i = 0; i < 16; i++) q[tid + i * 128] = __float2half(v[i] * inv);
}

// ============================================================================
// Contiguous row max over XT[b][q][0:2048] -> g_XMAX  (one warp per row)
// ============================================================================
__global__ __launch_bounds__(256) void maxpool_rows(const float* __restrict__ XT)
{
    const int r = blockIdx.x * 8 + (threadIdx.x >> 5);
    const int lane = threadIdx.x & 31;
    const float4* p = (const float4*)(XT + (size_t)r * SS);
    float m = -INFINITY;
#pragma unroll
    for (int i = 0; i < 16; i++) {
        float4 v = p[lane + i * 32];
        m = fmaxf(m, fmaxf(fmaxf(v.x, v.y), fmaxf(v.z, v.w)));
    }
#pragma unroll
    for (int o = 16; o > 0; o >>= 1) m = fmaxf(m, __shfl_xor_sync(0xffffffffu, m, o));
    if (lane == 0) g_XMAX[r] = m;
}

// ============================================================================
__global__ __launch_bounds__(256) void final_head(
    const float* __restrict__ W3, const float* __restrict__ b3,
    float* __restrict__ out)
{
    const int b = blockIdx.x;
    const int tid = threadIdx.x;
    __shared__ float xs[QDIM];
    xs[tid] = g_XMAX[b * QDIM + tid];
    __syncthreads();

#pragma unroll
    for (int kk = 0; kk < 4; kk++) {
        const int o = tid + kk * 256;
        const float4* w = (const float4*)(W3 + (size_t)o * QDIM);
        float acc = 0.f;
#pragma unroll
        for (int qq = 0; qq < QDIM / 4; qq++) {
            float4 wv = w[qq];
            acc += wv.x * xs[qq * 4 + 0] + wv.y * xs[qq * 4 + 1]
                 + wv.z * xs[qq * 4 + 2] + wv.w * xs[qq * 4 + 3];
        }
        out[(size_t)b * ODIM + o] = fmaxf(acc + b3[o], 0.f);
    }
}

// ============================================================================
extern "C" void kernel_launch(void* const* d_in, const int* in_sizes, int n_in,
                              void* d_out, int out_size)
{
    const float* data = (const float*)d_in[0];
    /* d_in[1] = seq_len: unused by the reference */
    const float* W1 = (const float*)d_in[2];
    const float* b1 = (const float*)d_in[3];
    const float* W2 = (const float*)d_in[4];
    const float* b2 = (const float*)d_in[5];
    const float* W3 = (const float*)d_in[6];
    const float* b3 = (const float*)d_in[7];
    float* out = (float*)d_out;

    __half *dataH, *W1h, *W2h, *Qh, *Kh, *KTh, *AH;
    float *SC, *XT;
    cudaGetSymbolAddress((void**)&dataH, g_dataH);
    cudaGetSymbolAddress((void**)&W1h, g_W1h);
    cudaGetSymbolAddress((void**)&W2h, g_W2h);
    cudaGetSymbolAddress((void**)&Qh,  g_Qh);
    cudaGetSymbolAddress((void**)&Kh,  g_Kh);
    cudaGetSymbolAddress((void**)&KTh, g_KTh);
    cudaGetSymbolAddress((void**)&SC,  g_SC);
    cudaGetSymbolAddress((void**)&AH,  g_AH);
    cudaGetSymbolAddress((void**)&XT,  g_XT);

    const int SMEM = STAGES * 10240 * 2;   // 81920 B
    cudaFuncSetAttribute(hgemm<0>, cudaFuncAttributeMaxDynamicSharedMemorySize, SMEM);
    cudaFuncSetAttribute(hgemm<1>, cudaFuncAttributeMaxDynamicSharedMemorySize, SMEM);
    cudaFuncSetAttribute(hgemm<2>, cudaFuncAttributeMaxDynamicSharedMemorySize, SMEM);

    const size_t strQK = (size_t)SS * QDIM;
    const size_t strSC = (size_t)SS * SS;
    const float  inv_sqrt_qd = 1.0f / 16.0f;

    // 0) convert inputs to fp16
    const size_t nd = (size_t)BB * SS * DD;
    f2h_kernel<<<(unsigned)(nd / (256 * 8)), 256>>>(data, dataH, nd);
    f2h_kernel<<<(QDIM * DD) / (256 * 8), 256>>>(W1, W1h, QDIM * DD);
    f2h_kernel<<<(QDIM * DD) / (256 * 8), 256>>>(W2, W2h, QDIM * DD);

    // 1) Q = data @ W1^T + b1 -> fp16
    hgemm<1><<<dim3(QDIM / 128, (BB * SS) / 128, 1), 256, SMEM>>>(
        dataH, W1h, b1, Qh, nullptr, DD, DD, QDIM, DD, 1.0f, 0, 0, 0);
    // 2) K = data @ W2^T + b2 -> fp16 + fp16 transposed
    hgemm<2><<<dim3(QDIM / 128, (BB * SS) / 128, 1), 256, SMEM>>>(
        dataH, W2h, b2, Kh, KTh, DD, DD, QDIM, DD, 1.0f, 0, 0, 0);

    // 3) scores[b] = (K[b] @ Q[b]^T) / 16 -> fp32
    hgemm<0><<<dim3(SS / 128, SS / 128, BB), 256, SMEM>>>(
        Kh, Qh, nullptr, SC, nullptr, QDIM, QDIM, SS, QDIM, inv_sqrt_qd,
        strQK, strQK, strSC);

    // 4) softmax -> fp16 probs
    softmax_rows<<<BB * SS, 128>>>(SC, AH);

    // 5) XT[b][q][s] = sum_j KT[b][q][j] * attn[b][s][j]  (NT, fp32 out)
    hgemm<0><<<dim3(SS / 128, QDIM / 128, BB), 256, SMEM>>>(
        KTh, AH, nullptr, XT, nullptr, SS, SS, SS, SS, 1.0f,
        strQK, strSC, strQK);

    // 6) maxpool over contiguous s
    maxpool_rows<<<BB * QDIM / 8, 256>>>(XT);

    // 7) out = relu(xmax @ W3^T + b3)
    final_head<<<BB, 256>>>(W3, b3, out);
}

// round 7
// speedup vs baseline: 5.3150x; 1.1027x over previous
#include <cuda_runtime.h>
#include <cuda_fp16.h>
#include <cstdint>

#define BB  32
#define SS  2048
#define DD  768
#define QDIM 256
#define ODIM 1024
#define STAGES 4

// -------- scratch (allocation-free: __device__ globals) --------
__device__ __half g_dataH[(size_t)BB * SS * DD];
__device__ __half g_W1h[QDIM * DD];
__device__ __half g_W2h[QDIM * DD];
__device__ __half g_Qh [(size_t)BB * SS * QDIM];
__device__ __half g_Kh [(size_t)BB * SS * QDIM];
__device__ __half g_KTh[(size_t)BB * QDIM * SS];   // K transposed [b][q][s]
__device__ __half g_EH [(size_t)BB * SS * SS];     // exp(scores) fp16 (256 MB)
__device__ float  g_RS [BB * SS];                  // row sums of exp
__device__ float  g_XT [(size_t)BB * QDIM * SS];   // attn out transposed [b][q][s]
__device__ float  g_XMAX[BB * QDIM];

__device__ __forceinline__ uint32_t smem_u32(const void* p) {
    uint32_t a;
    asm("{ .reg .u64 t; cvta.to.shared.u64 t, %1; cvt.u32.u64 %0, t; }" : "=r"(a) : "l"(p));
    return a;
}
__device__ __forceinline__ void cp16(uint32_t dst, const void* src) {
    asm volatile("cp.async.cg.shared.global [%0], [%1], 16;" :: "r"(dst), "l"(src));
}
#define CP_COMMIT() asm volatile("cp.async.commit_group;" ::: "memory")
#define CP_WAIT(n)  asm volatile("cp.async.wait_group %0;" :: "n"(n) : "memory")

__device__ __forceinline__ void ldsm4(uint32_t& r0, uint32_t& r1, uint32_t& r2,
                                      uint32_t& r3, uint32_t addr) {
    asm volatile("ldmatrix.sync.aligned.m8n8.x4.shared.b16 {%0,%1,%2,%3}, [%4];"
                 : "=r"(r0), "=r"(r1), "=r"(r2), "=r"(r3) : "r"(addr));
}

__device__ __forceinline__ void mma16(float* d, const uint32_t* a, const uint32_t* b) {
    asm volatile(
        "mma.sync.aligned.m16n8k16.row.col.f32.f16.f16.f32 "
        "{%0,%1,%2,%3}, {%4,%5,%6,%7}, {%8,%9}, {%0,%1,%2,%3};"
        : "+f"(d[0]), "+f"(d[1]), "+f"(d[2]), "+f"(d[3])
        : "r"(a[0]), "r"(a[1]), "r"(a[2]), "r"(a[3]), "r"(b[0]), "r"(b[1]));
}

// ============================================================================
// fp16 NT GEMM, cp.async 4-stage pipeline + ldmatrix fragment loads.
// CTA 128x128, k-chunk 32, 256 thr (8 warps 2x4), warp tile 64x32.
// A [M,K], B [N,K] fp16 row-major.
//   EPI=0: C fp32, *scale
//   EPI=1: C fp16, *scale + bias
//   EPI=2: C fp16 + bias, ALSO CT fp16 transposed per-batch [QDIM][SS] (proj-K)
//   EPI=3: C fp16 = exp(acc*scale); per-row sums atomically added to aux[b*SS+m]
//   EPI=4: C fp32 = acc*scale / aux[b*SS+n]   (column-wise normalization)
// Smem rows padded to 40 halves (80B): conflict-free ldmatrix.
// Requires M%128==0, N%128==0, kdim%32==0.
// ============================================================================
template <int EPI>
__global__ __launch_bounds__(256, 2) void hgemm(
    const __half* __restrict__ A, const __half* __restrict__ B,
    const float* __restrict__ bias, void* __restrict__ Cv,
    __half* __restrict__ CT, float* __restrict__ aux,
    int lda, int ldb, int ldc, int kdim, float scale,
    size_t sA, size_t sB, size_t sC)
{
    extern __shared__ __half sm[];
    A += (size_t)blockIdx.z * sA;
    B += (size_t)blockIdx.z * sB;
    const int bm = blockIdx.y * 128;
    const int bn = blockIdx.x * 128;

    const int tid = threadIdx.x;
    const int lane = tid & 31, wid = tid >> 5;
    const int wm = wid & 1, wn = wid >> 1;      // warp 64m x 32n
    const int qd = lane >> 2, cc = lane & 3;

    // loader: thread covers row = tid>>1, halves [seg, seg+16)
    const int lrow = tid >> 1;
    const int lseg = (tid & 1) * 16;
    const __half* pa = A + (size_t)(bm + lrow) * lda + lseg;
    const __half* pb = B + (size_t)(bn + lrow) * ldb + lseg;
    const uint32_t smb = smem_u32(sm);
    const uint32_t dA = smb + (uint32_t)(lrow * 40 + lseg) * 2;
    const uint32_t dB = dA + 5120 * 2;
    const uint32_t STG = 10240 * 2;             // bytes per stage (A+B)

    // ldmatrix per-lane offsets (relative to stage base, ks=0)
    uint32_t aoff[4], boff[2];
#pragma unroll
    for (int mt = 0; mt < 4; mt++)
        aoff[mt] = (uint32_t)(((wm * 64 + mt * 16 + (lane & 7) + (lane & 8)) * 40
                               + ((lane >> 4) * 8)) * 2);
#pragma unroll
    for (int np = 0; np < 2; np++)
        boff[np] = (uint32_t)(5120 * 2
                   + ((wn * 32 + np * 16 + (lane & 7) + ((lane >> 4) * 8)) * 40
                      + (lane & 8)) * 2);

    float acc[4][4][4];
#pragma unroll
    for (int i = 0; i < 4; i++)
#pragma unroll
        for (int j = 0; j < 4; j++)
#pragma unroll
            for (int r = 0; r < 4; r++) acc[i][j][r] = 0.f;

    const int nc = kdim >> 5;

    // prologue: stages 0..STAGES-2
#pragma unroll
    for (int s = 0; s < STAGES - 1; s++) {
        if (s < nc) {
            const size_t k0 = (size_t)s * 32;
            const uint32_t da = dA + s * STG, db = dB + s * STG;
            cp16(da,      pa + k0);
            cp16(da + 16, pa + k0 + 8);
            cp16(db,      pb + k0);
            cp16(db + 16, pb + k0 + 8);
        }
        CP_COMMIT();
    }

    for (int ch = 0; ch < nc; ch++) {
        CP_WAIT(STAGES - 2);
        __syncthreads();   // stage ch ready; everyone done reading stage ch-1

        // refill the stage freed by chunk ch-1
        {
            const int nxt = ch + STAGES - 1;
            if (nxt < nc) {
                const int st = nxt & (STAGES - 1);
                const size_t k0 = (size_t)nxt * 32;
                const uint32_t da = dA + st * STG, db = dB + st * STG;
                cp16(da,      pa + k0);
                cp16(da + 16, pa + k0 + 8);
                cp16(db,      pb + k0);
                cp16(db + 16, pb + k0 + 8);
            }
            CP_COMMIT();
        }

        const uint32_t sa = smb + (uint32_t)(ch & (STAGES - 1)) * STG;
#pragma unroll
        for (int ks = 0; ks < 2; ks++) {
            uint32_t af[4][4], bf[4][2];
#pragma unroll
            for (int mt = 0; mt < 4; mt++)
                ldsm4(af[mt][0], af[mt][1], af[mt][2], af[mt][3],
                      sa + aoff[mt] + ks * 32);
#pragma unroll
            for (int np = 0; np < 2; np++)
                ldsm4(bf[2 * np][0], bf[2 * np][1], bf[2 * np + 1][0],
                      bf[2 * np + 1][1], sa + boff[np] + ks * 32);
#pragma unroll
            for (int mt = 0; mt < 4; mt++)
#pragma unroll
                for (int nt = 0; nt < 4; nt++)
                    mma16(acc[mt][nt], af[mt], bf[nt]);
        }
    }

    // ---- epilogue ----
    float inv[4][2];
    if (EPI == 4) {
#pragma unroll
        for (int nt = 0; nt < 4; nt++) {
            const int n0 = bn + wn * 32 + nt * 8 + cc * 2;
            inv[nt][0] = 1.0f / __ldg(&aux[blockIdx.z * SS + n0]);
            inv[nt][1] = 1.0f / __ldg(&aux[blockIdx.z * SS + n0 + 1]);
        }
    }
    float* srs = (float*)sm;   // EPI==3: per-CTA row sums (128 floats)
    if (EPI == 3) {
        __syncthreads();       // all warps done reading pipeline smem
        if (tid < 128) srs[tid] = 0.f;
        __syncthreads();
    }

#pragma unroll
    for (int mt = 0; mt < 4; mt++) {
        const int m0 = bm + wm * 64 + mt * 16 + qd;
        float rs0 = 0.f, rs1 = 0.f;
#pragma unroll
        for (int nt = 0; nt < 4; nt++) {
            const int n0 = bn + wn * 32 + nt * 8 + cc * 2;
            float c0 = acc[mt][nt][0] * scale;
            float c1 = acc[mt][nt][1] * scale;
            float c2 = acc[mt][nt][2] * scale;
            float c3 = acc[mt][nt][3] * scale;
            if (EPI == 0 || EPI == 4) {
                if (EPI == 4) {
                    c0 *= inv[nt][0]; c1 *= inv[nt][1];
                    c2 *= inv[nt][0]; c3 *= inv[nt][1];
                }
                float* Cf = (float*)Cv + (size_t)blockIdx.z * sC;
                *(float2*)(Cf + (size_t)m0 * ldc + n0)       = make_float2(c0, c1);
                *(float2*)(Cf + (size_t)(m0 + 8) * ldc + n0) = make_float2(c2, c3);
            } else if (EPI == 3) {
                c0 = __expf(c0); c1 = __expf(c1);
                c2 = __expf(c2); c3 = __expf(c3);
                rs0 += c0 + c1; rs1 += c2 + c3;
                __half2 h0 = __floats2half2_rn(c0, c1);
                __half2 h1 = __floats2half2_rn(c2, c3);
                __half* Ch = (__half*)Cv + (size_t)blockIdx.z * sC;
                *(__half2*)(Ch + (size_t)m0 * ldc + n0)       = h0;
                *(__half2*)(Ch + (size_t)(m0 + 8) * ldc + n0) = h1;
            } else {
                const float bx = bias[n0], by = bias[n0 + 1];
                c0 += bx; c1 += by; c2 += bx; c3 += by;
                __half2 h0 = __floats2half2_rn(c0, c1);
                __half2 h1 = __floats2half2_rn(c2, c3);
                __half* Ch = (__half*)Cv + (size_t)blockIdx.z * sC;
                *(__half2*)(Ch + (size_t)m0 * ldc + n0)       = h0;
                *(__half2*)(Ch + (size_t)(m0 + 8) * ldc + n0) = h1;
                if (EPI == 2) {
                    const int b0 = m0 >> 11, s0 = m0 & (SS - 1);
                    __half* t = CT + ((size_t)b0 * QDIM + n0) * SS + s0;
                    t[0]      = __low2half(h0);
                    t[SS]     = __high2half(h0);
                    t[8]      = __low2half(h1);
                    t[SS + 8] = __high2half(h1);
                }
            }
        }
        if (EPI == 3) {
            // reduce the 32-col partial across the 4 cc lanes of this row group
            rs0 += __shfl_xor_sync(0xffffffffu, rs0, 1);
            rs0 += __shfl_xor_sync(0xffffffffu, rs0, 2);
            rs1 += __shfl_xor_sync(0xffffffffu, rs1, 1);
            rs1 += __shfl_xor_sync(0xffffffffu, rs1, 2);
            if (cc == 0) {
                atomicAdd(&srs[wm * 64 + mt * 16 + qd],     rs0);
                atomicAdd(&srs[wm * 64 + mt * 16 + qd + 8], rs1);
            }
        }
    }
    if (EPI == 3) {
        __syncthreads();
        if (tid < 128) atomicAdd(&aux[blockIdx.z * SS + bm + tid], srs[tid]);
    }
}

// ============================================================================
__global__ __launch_bounds__(256) void zero_rowsum(float* __restrict__ rs)
{
    const int i = blockIdx.x * 1024 + threadIdx.x * 4;
    *(float4*)(rs + i) = make_float4(0.f, 0.f, 0.f, 0.f);
}

// ============================================================================
// fp32 -> fp16 conversion (n % 8 == 0)
// ============================================================================
__global__ __launch_bounds__(256) void f2h_kernel(
    const float* __restrict__ s, __half* __restrict__ d, size_t n)
{
    const size_t i = ((size_t)blockIdx.x * 256 + threadIdx.x) * 8;
    if (i + 8 <= n) {
        float4 a = *(const float4*)(s + i);
        float4 b = *(const float4*)(s + i + 4);
        uint4 o;
        __half2 h;
        h = __floats2half2_rn(a.x, a.y); o.x = *(uint32_t*)&h;
        h = __floats2half2_rn(a.z, a.w); o.y = *(uint32_t*)&h;
        h = __floats2half2_rn(b.x, b.y); o.z = *(uint32_t*)&h;
        h = __floats2half2_rn(b.z, b.w); o.w = *(uint32_t*)&h;
        *(uint4*)(d + i) = o;
    }
}

// ============================================================================
// Contiguous row max over XT[b][q][0:2048] -> g_XMAX  (one warp per row)
// ============================================================================
__global__ __launch_bounds__(256) void maxpool_rows(const float* __restrict__ XT)
{
    const int r = blockIdx.x * 8 + (threadIdx.x >> 5);
    const int lane = threadIdx.x & 31;
    const float4* p = (const float4*)(XT + (size_t)r * SS);
    float m = -INFINITY;
#pragma unroll
    for (int i = 0; i < 16; i++) {
        float4 v = p[lane + i * 32];
        m = fmaxf(m, fmaxf(fmaxf(v.x, v.y), fmaxf(v.z, v.w)));
    }
#pragma unroll
    for (int o = 16; o > 0; o >>= 1) m = fmaxf(m, __shfl_xor_sync(0xffffffffu, m, o));
    if (lane == 0) g_XMAX[r] = m;
}

// ============================================================================
__global__ __launch_bounds__(256) void final_head(
    const float* __restrict__ W3, const float* __restrict__ b3,
    float* __restrict__ out)
{
    const int b = blockIdx.x;
    const int tid = threadIdx.x;
    __shared__ float xs[QDIM];
    xs[tid] = g_XMAX[b * QDIM + tid];
    __syncthreads();

#pragma unroll
    for (int kk = 0; kk < 4; kk++) {
        const int o = tid + kk * 256;
        const float4* w = (const float4*)(W3 + (size_t)o * QDIM);
        float acc = 0.f;
#pragma unroll
        for (int qq = 0; qq < QDIM / 4; qq++) {
            float4 wv = w[qq];
            acc += wv.x * xs[qq * 4 + 0] + wv.y * xs[qq * 4 + 1]
                 + wv.z * xs[qq * 4 + 2] + wv.w * xs[qq * 4 + 3];
        }
        out[(size_t)b * ODIM + o] = fmaxf(acc + b3[o], 0.f);
    }
}

// ============================================================================
extern "C" void kernel_launch(void* const* d_in, const int* in_sizes, int n_in,
                              void* d_out, int out_size)
{
    const float* data = (const float*)d_in[0];
    /* d_in[1] = seq_len: unused by the reference */
    const float* W1 = (const float*)d_in[2];
    const float* b1 = (const float*)d_in[3];
    const float* W2 = (const float*)d_in[4];
    const float* b2 = (const float*)d_in[5];
    const float* W3 = (const float*)d_in[6];
    const float* b3 = (const float*)d_in[7];
    float* out = (float*)d_out;

    __half *dataH, *W1h, *W2h, *Qh, *Kh, *KTh, *EH;
    float *RS, *XT;
    cudaGetSymbolAddress((void**)&dataH, g_dataH);
    cudaGetSymbolAddress((void**)&W1h, g_W1h);
    cudaGetSymbolAddress((void**)&W2h, g_W2h);
    cudaGetSymbolAddress((void**)&Qh,  g_Qh);
    cudaGetSymbolAddress((void**)&Kh,  g_Kh);
    cudaGetSymbolAddress((void**)&KTh, g_KTh);
    cudaGetSymbolAddress((void**)&EH,  g_EH);
    cudaGetSymbolAddress((void**)&RS,  g_RS);
    cudaGetSymbolAddress((void**)&XT,  g_XT);

    const int SMEM = STAGES * 10240 * 2;   // 81920 B
    cudaFuncSetAttribute(hgemm<1>, cudaFuncAttributeMaxDynamicSharedMemorySize, SMEM);
    cudaFuncSetAttribute(hgemm<2>, cudaFuncAttributeMaxDynamicSharedMemorySize, SMEM);
    cudaFuncSetAttribute(hgemm<3>, cudaFuncAttributeMaxDynamicSharedMemorySize, SMEM);
    cudaFuncSetAttribute(hgemm<4>, cudaFuncAttributeMaxDynamicSharedMemorySize, SMEM);

    const size_t strQK = (size_t)SS * QDIM;
    const size_t strSC = (size_t)SS * SS;
    const float  inv_sqrt_qd = 1.0f / 16.0f;

    // 0) convert inputs to fp16; zero rowsum accumulator
    const size_t nd = (size_t)BB * SS * DD;
    f2h_kernel<<<(unsigned)(nd / (256 * 8)), 256>>>(data, dataH, nd);
    f2h_kernel<<<(QDIM * DD) / (256 * 8), 256>>>(W1, W1h, QDIM * DD);
    f2h_kernel<<<(QDIM * DD) / (256 * 8), 256>>>(W2, W2h, QDIM * DD);
    zero_rowsum<<<(BB * SS) / 1024, 256>>>(RS);

    // 1) Q = data @ W1^T + b1 -> fp16
    hgemm<1><<<dim3(QDIM / 128, (BB * SS) / 128, 1), 256, SMEM>>>(
        dataH, W1h, b1, Qh, nullptr, nullptr, DD, DD, QDIM, DD, 1.0f, 0, 0, 0);
    // 2) K = data @ W2^T + b2 -> fp16 + fp16 transposed
    hgemm<2><<<dim3(QDIM / 128, (BB * SS) / 128, 1), 256, SMEM>>>(
        dataH, W2h, b2, Kh, KTh, nullptr, DD, DD, QDIM, DD, 1.0f, 0, 0, 0);

    // 3) E[b] = exp((K[b] @ Q[b]^T) / 16) -> fp16, rowsums into RS
    hgemm<3><<<dim3(SS / 128, SS / 128, BB), 256, SMEM>>>(
        Kh, Qh, nullptr, EH, nullptr, RS, QDIM, QDIM, SS, QDIM, inv_sqrt_qd,
        strQK, strQK, strSC);

    // 4) XT[b][q][s] = (sum_j KT[b][q][j] * E[s][j]) / RS[b][s]  (NT, fp32 out)
    hgemm<4><<<dim3(SS / 128, QDIM / 128, BB), 256, SMEM>>>(
        KTh, EH, nullptr, XT, nullptr, RS, SS, SS, SS, SS, 1.0f,
        strQK, strSC, strQK);

    // 5) maxpool over contiguous s
    maxpool_rows<<<BB * QDIM / 8, 256>>>(XT);

    // 6) out = relu(xmax @ W3^T + b3)
    final_head<<<BB, 256>>>(W3, b3, out);
}